// round 2
// baseline (speedup 1.0000x reference)
#include <cuda_runtime.h>
#include <math.h>

#define VN 50000
#define EN 300
#define HN 2048
#define LN 512
#define EH 2348   // E + H
#define H3 6144   // 3*H

// ---- scratch (device globals; no allocation allowed) ----
__device__ float g_attn_logits[LN];
__device__ float g_attn_w[LN];
__device__ float g_gh[H3];
__device__ float g_attn_part[8 * HN];
__device__ float g_attn_applied[HN];
__device__ float g_x[HN];
__device__ float g_hnew[HN];
__device__ float g_vlogits[VN];
__device__ unsigned g_maxbits;
__device__ float g_psum[256];
__device__ float g_logZ;

__device__ __forceinline__ float warpSum(float v) {
#pragma unroll
    for (int o = 16; o; o >>= 1) v += __shfl_xor_sync(0xffffffffu, v, o);
    return v;
}

// order-preserving float<->uint encoding for deterministic atomicMax
__device__ __forceinline__ unsigned fenc(float f) {
    unsigned b = __float_as_uint(f);
    return (b & 0x80000000u) ? ~b : (b | 0x80000000u);
}
__device__ __forceinline__ float fdec(unsigned u) {
    unsigned b = (u & 0x80000000u) ? (u ^ 0x80000000u) : ~u;
    return __uint_as_float(b);
}

__global__ void k_init() { g_maxbits = 0u; }

// Attention logits (512 rows of dot over E+H) and gh = W_hh @ h0 + b_hh (6144 rows).
// One 256-thread block per row.
__global__ void k_attnlogits_gh(const int* tok_p, const float* hid, const float* emb,
                                const float* attn_W, const float* attn_b,
                                const float* W_hh, const float* b_hh) {
    int b = blockIdx.x, t = threadIdx.x;
    const float4* h4 = (const float4*)hid;
    float s = 0.f;
    if (b < LN) {
        const float* row = attn_W + (long)b * EH;
        const float* e = emb + (long)(*tok_p) * EN;
        for (int i = t; i < EN; i += 256) s += row[i] * e[i];
        const float4* r4 = (const float4*)(row + EN);
#pragma unroll 4
        for (int i = t; i < HN / 4; i += 256) {
            float4 a = r4[i], c = h4[i];
            s += a.x * c.x + a.y * c.y + a.z * c.z + a.w * c.w;
        }
    } else {
        int r = b - LN;
        const float4* r4 = (const float4*)(W_hh + (long)r * HN);
#pragma unroll 4
        for (int i = t; i < HN / 4; i += 256) {
            float4 a = r4[i], c = h4[i];
            s += a.x * c.x + a.y * c.y + a.z * c.z + a.w * c.w;
        }
    }
    __shared__ float sh[8];
    s = warpSum(s);
    if ((t & 31) == 0) sh[t >> 5] = s;
    __syncthreads();
    if (t == 0) {
        float v = 0.f;
#pragma unroll
        for (int i = 0; i < 8; i++) v += sh[i];
        if (b < LN) g_attn_logits[b] = v + attn_b[b];
        else        g_gh[b - LN]     = v + b_hh[b - LN];
    }
}

// softmax over 512 attn logits; single block of 512 threads
__global__ void k_softmax_attn(float* out) {
    __shared__ float red[LN];
    int t = threadIdx.x;
    float v = g_attn_logits[t];
    red[t] = v;
    __syncthreads();
    for (int s = 256; s > 0; s >>= 1) {
        if (t < s) red[t] = fmaxf(red[t], red[t + s]);
        __syncthreads();
    }
    float m = red[0];
    __syncthreads();
    float e = expf(v - m);
    red[t] = e;
    __syncthreads();
    for (int s = 256; s > 0; s >>= 1) {
        if (t < s) red[t] += red[t + s];
        __syncthreads();
    }
    float w = e / red[0];
    g_attn_w[t] = w;
    out[VN + HN + t] = w;   // attn_weights output
}

// attn_applied = w @ encoder_outputs, split over 8 L-chunks for parallelism
__global__ void k_attnapply_part(const float* enc) {
    __shared__ float wsh[64];
    int t = threadIdx.x;
    int chunk = blockIdx.x >> 3, cg = blockIdx.x & 7;
    if (t < 64) wsh[t] = g_attn_w[chunk * 64 + t];
    __syncthreads();
    int h = cg * 256 + t;
    const float* base = enc + (long)chunk * 64 * HN + h;
    float s = 0.f;
#pragma unroll 8
    for (int l = 0; l < 64; l++) s += wsh[l] * base[(long)l * HN];
    g_attn_part[chunk * HN + h] = s;
}

__global__ void k_attnapply_sum() {
    int h = blockIdx.x * 256 + threadIdx.x;
    float s = 0.f;
#pragma unroll
    for (int c = 0; c < 8; c++) s += g_attn_part[c * HN + h];
    g_attn_applied[h] = s;
}

// x = relu(comb_W @ [embedded, attn_applied] + comb_b); block per output row
__global__ void k_combine(const int* tok_p, const float* emb,
                          const float* comb_W, const float* comb_b) {
    int h = blockIdx.x, t = threadIdx.x;
    const float* row = comb_W + (long)h * EH;
    const float* e = emb + (long)(*tok_p) * EN;
    float s = 0.f;
    for (int i = t; i < EN; i += 256) s += row[i] * e[i];
    const float4* r4 = (const float4*)(row + EN);
    const float4* a4 = (const float4*)g_attn_applied;
#pragma unroll 2
    for (int i = t; i < HN / 4; i += 256) {
        float4 a = r4[i], c = a4[i];
        s += a.x * c.x + a.y * c.y + a.z * c.z + a.w * c.w;
    }
    __shared__ float sh[8];
    s = warpSum(s);
    if ((t & 31) == 0) sh[t >> 5] = s;
    __syncthreads();
    if (t == 0) {
        float v = 0.f;
#pragma unroll
        for (int i = 0; i < 8; i++) v += sh[i];
        g_x[h] = fmaxf(v + comb_b[h], 0.f);
    }
}

// fused GRU: block per h computes 3 dots (r,z,n rows of W_ih) + gate math
__global__ void k_gru(const float* hid, const float* W_ih, const float* b_ih, float* out) {
    int h = blockIdx.x, t = threadIdx.x;
    __shared__ float4 x4s[HN / 4];
    const float4* x4 = (const float4*)g_x;
    x4s[t] = x4[t];
    x4s[t + 256] = x4[t + 256];
    __syncthreads();
    const float4* wr = (const float4*)(W_ih + (long)h * HN);
    const float4* wz = (const float4*)(W_ih + (long)(h + HN) * HN);
    const float4* wn = (const float4*)(W_ih + (long)(h + 2 * HN) * HN);
    float sr = 0.f, sz = 0.f, sn = 0.f;
#pragma unroll 2
    for (int i = t; i < HN / 4; i += 256) {
        float4 c = x4s[i];
        float4 a = wr[i]; sr += a.x * c.x + a.y * c.y + a.z * c.z + a.w * c.w;
        float4 b = wz[i]; sz += b.x * c.x + b.y * c.y + b.z * c.z + b.w * c.w;
        float4 d = wn[i]; sn += d.x * c.x + d.y * c.y + d.z * c.z + d.w * c.w;
    }
    __shared__ float sh[3][8];
    sr = warpSum(sr); sz = warpSum(sz); sn = warpSum(sn);
    if ((t & 31) == 0) { sh[0][t >> 5] = sr; sh[1][t >> 5] = sz; sh[2][t >> 5] = sn; }
    __syncthreads();
    if (t == 0) {
        float ir = 0.f, iz = 0.f, inn = 0.f;
#pragma unroll
        for (int i = 0; i < 8; i++) { ir += sh[0][i]; iz += sh[1][i]; inn += sh[2][i]; }
        ir += b_ih[h]; iz += b_ih[h + HN]; inn += b_ih[h + 2 * HN];
        float hr = g_gh[h], hz = g_gh[h + HN], hn = g_gh[h + 2 * HN];
        float r = 1.f / (1.f + expf(-(ir + hr)));
        float z = 1.f / (1.f + expf(-(iz + hz)));
        float n = tanhf(inn + r * hn);
        float hv = (1.f - z) * n + z * hid[h];
        g_hnew[h] = hv;
        out[VN + h] = hv;   // h_new output
    }
}

// output logits: warp per row, 8 rows per block, h_new staged in shared
__global__ void k_logits(const float* out_W, const float* out_b) {
    __shared__ float4 h4s[HN / 4];
    __shared__ float wmax[8];
    int t = threadIdx.x;
    const float4* h4 = (const float4*)g_hnew;
    h4s[t] = h4[t];
    h4s[t + 256] = h4[t + 256];
    __syncthreads();
    int lane = t & 31, warp = t >> 5;
    int row = blockIdx.x * 8 + warp;
    const float4* w4 = (const float4*)(out_W + (long)row * HN);
    float s = 0.f;
#pragma unroll
    for (int k = 0; k < 16; k++) {
        float4 a = w4[lane + 32 * k];
        float4 c = h4s[lane + 32 * k];
        s += a.x * c.x + a.y * c.y + a.z * c.z + a.w * c.w;
    }
    s = warpSum(s);
    if (lane == 0) {
        s += out_b[row];
        g_vlogits[row] = s;
        wmax[warp] = s;
    }
    __syncthreads();
    if (t == 0) {
        float m = wmax[0];
#pragma unroll
        for (int i = 1; i < 8; i++) m = fmaxf(m, wmax[i]);
        atomicMax(&g_maxbits, fenc(m));   // deterministic (max is order-independent)
    }
}

// deterministic two-stage log-sum-exp
__global__ void k_expsum() {
    int i = blockIdx.x * 256 + threadIdx.x;
    float m = fdec(g_maxbits);
    float e = (i < VN) ? expf(g_vlogits[i] - m) : 0.f;
    __shared__ float sh[8];
    float s = warpSum(e);
    int t = threadIdx.x;
    if ((t & 31) == 0) sh[t >> 5] = s;
    __syncthreads();
    if (t == 0) {
        float v = 0.f;
#pragma unroll
        for (int j = 0; j < 8; j++) v += sh[j];
        g_psum[blockIdx.x] = v;
    }
}

__global__ void k_logz(int nblocks) {
    int t = threadIdx.x;
    float v = (t < nblocks) ? g_psum[t] : 0.f;
    __shared__ float sh[8];
    float s = warpSum(v);
    if ((t & 31) == 0) sh[t >> 5] = s;
    __syncthreads();
    if (t == 0) {
        float tot = 0.f;
#pragma unroll
        for (int j = 0; j < 8; j++) tot += sh[j];
        g_logZ = fdec(g_maxbits) + logf(tot);
    }
}

__global__ void k_writeout(float* out) {
    int i = blockIdx.x * 256 + threadIdx.x;
    if (i < VN) out[i] = g_vlogits[i] - g_logZ;
}

extern "C" void kernel_launch(void* const* d_in, const int* in_sizes, int n_in,
                              void* d_out, int out_size) {
    const int*   tok    = (const int*)d_in[0];
    const float* hid    = (const float*)d_in[1];
    const float* enc    = (const float*)d_in[2];
    const float* emb    = (const float*)d_in[3];
    const float* attn_W = (const float*)d_in[4];
    const float* attn_b = (const float*)d_in[5];
    const float* comb_W = (const float*)d_in[6];
    const float* comb_b = (const float*)d_in[7];
    const float* W_ih   = (const float*)d_in[8];
    const float* W_hh   = (const float*)d_in[9];
    const float* b_ih   = (const float*)d_in[10];
    const float* b_hh   = (const float*)d_in[11];
    const float* out_W  = (const float*)d_in[12];
    const float* out_b  = (const float*)d_in[13];
    float* out = (float*)d_out;

    const int NB = (VN + 255) / 256;  // 196

    k_init<<<1, 1>>>();
    k_attnlogits_gh<<<LN + H3, 256>>>(tok, hid, emb, attn_W, attn_b, W_hh, b_hh);
    k_softmax_attn<<<1, LN>>>(out);
    k_attnapply_part<<<64, 256>>>(enc);
    k_attnapply_sum<<<HN / 256, 256>>>();
    k_combine<<<HN, 256>>>(tok, emb, comb_W, comb_b);
    k_gru<<<HN, 256>>>(hid, W_ih, b_ih, out);
    k_logits<<<VN / 8, 256>>>(out_W, out_b);
    k_expsum<<<NB, 256>>>();
    k_logz<<<1, 256>>>(NB);
    k_writeout<<<NB, 256>>>(out);
}

// round 3
// speedup vs baseline: 1.0351x; 1.0351x over previous
#include <cuda_runtime.h>
#include <math.h>

#define VN 50000
#define EN 300
#define HN 2048
#define LN 512
#define EH 2348   // E + H
#define H3 6144   // 3*H
#define NCHUNK 32         // L-chunks for attnapply
#define LPC 16            // L rows per chunk
#define LOGITS_ROWS 16
#define NLB (VN / LOGITS_ROWS)   // 3125 logits blocks

// ---- scratch (device globals; no allocation allowed) ----
__device__ float g_attn_logits[LN];
__device__ float g_gh[H3];
__device__ float g_attn_part[NCHUNK * HN];
__device__ float g_attn_applied[HN];
__device__ float g_x[HN];
__device__ float g_hnew[HN];
__device__ float g_vlogits[VN];
__device__ unsigned g_maxbits;
__device__ float g_bmax[NLB];
__device__ float g_bsum[NLB];
__device__ float g_logZ;

__device__ __forceinline__ float warpSum(float v) {
#pragma unroll
    for (int o = 16; o; o >>= 1) v += __shfl_xor_sync(0xffffffffu, v, o);
    return v;
}

// order-preserving float<->uint encoding for deterministic atomicMax
__device__ __forceinline__ unsigned fenc(float f) {
    unsigned b = __float_as_uint(f);
    return (b & 0x80000000u) ? ~b : (b | 0x80000000u);
}
__device__ __forceinline__ float fdec(unsigned u) {
    unsigned b = (u & 0x80000000u) ? (u ^ 0x80000000u) : ~u;
    return __uint_as_float(b);
}

// Attention logits (512 rows of dot over E+H) and gh = W_hh @ h0 + b_hh (6144 rows).
// One 256-thread block per row. Also zeroes g_maxbits (block 0).
__global__ void k_attnlogits_gh(const int* tok_p, const float* hid, const float* emb,
                                const float* attn_W, const float* attn_b,
                                const float* W_hh, const float* b_hh) {
    int b = blockIdx.x, t = threadIdx.x;
    if (b == 0 && t == 0) g_maxbits = 0u;
    const float4* h4 = (const float4*)hid;
    float s = 0.f;
    if (b < LN) {
        const float* row = attn_W + (long)b * EH;
        const float* e = emb + (long)(*tok_p) * EN;
        for (int i = t; i < EN; i += 256) s += row[i] * e[i];
        const float4* r4 = (const float4*)(row + EN);
#pragma unroll 2
        for (int i = t; i < HN / 4; i += 256) {
            float4 a = r4[i], c = h4[i];
            s += a.x * c.x + a.y * c.y + a.z * c.z + a.w * c.w;
        }
    } else {
        int r = b - LN;
        const float4* r4 = (const float4*)(W_hh + (long)r * HN);
#pragma unroll 2
        for (int i = t; i < HN / 4; i += 256) {
            float4 a = r4[i], c = h4[i];
            s += a.x * c.x + a.y * c.y + a.z * c.z + a.w * c.w;
        }
    }
    __shared__ float sh[8];
    s = warpSum(s);
    if ((t & 31) == 0) sh[t >> 5] = s;
    __syncthreads();
    if (t == 0) {
        float v = 0.f;
#pragma unroll
        for (int i = 0; i < 8; i++) v += sh[i];
        if (b < LN) g_attn_logits[b] = v + attn_b[b];
        else        g_gh[b - LN]     = v + b_hh[b - LN];
    }
}

// Fused softmax + attn_applied partials. Every block recomputes the 512-wide
// softmax from g_attn_logits (cheap, deterministic, identical across blocks),
// then applies its L-chunk to a 1024-float h-slice via float4 loads.
// grid = NCHUNK * 2 = 64 blocks, 256 threads.
__global__ void k_attnapply(const float* enc, float* out) {
    __shared__ float esh[LN];
    __shared__ float red[256];
    int t = threadIdx.x;
    float v0 = g_attn_logits[t], v1 = g_attn_logits[t + 256];
    red[t] = fmaxf(v0, v1);
    __syncthreads();
    for (int s = 128; s; s >>= 1) {
        if (t < s) red[t] = fmaxf(red[t], red[t + s]);
        __syncthreads();
    }
    float m = red[0];
    __syncthreads();
    float e0 = expf(v0 - m), e1 = expf(v1 - m);
    esh[t] = e0; esh[t + 256] = e1;
    red[t] = e0 + e1;
    __syncthreads();
    for (int s = 128; s; s >>= 1) {
        if (t < s) red[t] += red[t + s];
        __syncthreads();
    }
    float inv = 1.f / red[0];

    if (blockIdx.x == 0) {  // attn_weights output
        out[VN + HN + t]       = esh[t] * inv;
        out[VN + HN + t + 256] = esh[t + 256] * inv;
    }

    int chunk = blockIdx.x >> 1, half = blockIdx.x & 1;
    int h4 = half * 256 + t;                       // float4 index into H
    const float4* base = (const float4*)enc + (long)chunk * LPC * (HN / 4) + h4;
    float4 acc = make_float4(0.f, 0.f, 0.f, 0.f);
#pragma unroll
    for (int l = 0; l < LPC; l++) {
        float w = esh[chunk * LPC + l] * inv;
        float4 a = base[(long)l * (HN / 4)];
        acc.x += w * a.x; acc.y += w * a.y; acc.z += w * a.z; acc.w += w * a.w;
    }
    ((float4*)g_attn_part)[chunk * (HN / 4) + h4] = acc;
}

__global__ void k_attnapply_sum() {
    int h = blockIdx.x * 256 + threadIdx.x;
    float s = 0.f;
#pragma unroll
    for (int c = 0; c < NCHUNK; c++) s += g_attn_part[c * HN + h];
    g_attn_applied[h] = s;
}

// x = relu(comb_W @ [embedded, attn_applied] + comb_b); block per output row
__global__ void k_combine(const int* tok_p, const float* emb,
                          const float* comb_W, const float* comb_b) {
    int h = blockIdx.x, t = threadIdx.x;
    const float* row = comb_W + (long)h * EH;
    const float* e = emb + (long)(*tok_p) * EN;
    float s = 0.f;
    for (int i = t; i < EN; i += 256) s += row[i] * e[i];
    const float4* r4 = (const float4*)(row + EN);
    const float4* a4 = (const float4*)g_attn_applied;
#pragma unroll 2
    for (int i = t; i < HN / 4; i += 256) {
        float4 a = r4[i], c = a4[i];
        s += a.x * c.x + a.y * c.y + a.z * c.z + a.w * c.w;
    }
    __shared__ float sh[8];
    s = warpSum(s);
    if ((t & 31) == 0) sh[t >> 5] = s;
    __syncthreads();
    if (t == 0) {
        float v = 0.f;
#pragma unroll
        for (int i = 0; i < 8; i++) v += sh[i];
        g_x[h] = fmaxf(v + comb_b[h], 0.f);
    }
}

// fused GRU: block per h computes 3 dots (r,z,n rows of W_ih) + gate math
__global__ void k_gru(const float* hid, const float* W_ih, const float* b_ih, float* out) {
    int h = blockIdx.x, t = threadIdx.x;
    __shared__ float4 x4s[HN / 4];
    const float4* x4 = (const float4*)g_x;
    x4s[t] = x4[t];
    x4s[t + 256] = x4[t + 256];
    __syncthreads();
    const float4* wr = (const float4*)(W_ih + (long)h * HN);
    const float4* wz = (const float4*)(W_ih + (long)(h + HN) * HN);
    const float4* wn = (const float4*)(W_ih + (long)(h + 2 * HN) * HN);
    float sr = 0.f, sz = 0.f, sn = 0.f;
#pragma unroll 2
    for (int i = t; i < HN / 4; i += 256) {
        float4 c = x4s[i];
        float4 a = wr[i]; sr += a.x * c.x + a.y * c.y + a.z * c.z + a.w * c.w;
        float4 b = wz[i]; sz += b.x * c.x + b.y * c.y + b.z * c.z + b.w * c.w;
        float4 d = wn[i]; sn += d.x * c.x + d.y * c.y + d.z * c.z + d.w * c.w;
    }
    __shared__ float sh[3][8];
    sr = warpSum(sr); sz = warpSum(sz); sn = warpSum(sn);
    if ((t & 31) == 0) { sh[0][t >> 5] = sr; sh[1][t >> 5] = sz; sh[2][t >> 5] = sn; }
    __syncthreads();
    if (t == 0) {
        float ir = 0.f, iz = 0.f, inn = 0.f;
#pragma unroll
        for (int i = 0; i < 8; i++) { ir += sh[0][i]; iz += sh[1][i]; inn += sh[2][i]; }
        ir += b_ih[h]; iz += b_ih[h + HN]; inn += b_ih[h + 2 * HN];
        float hr = g_gh[h], hz = g_gh[h + HN], hn = g_gh[h + 2 * HN];
        float r = 1.f / (1.f + expf(-(ir + hr)));
        float z = 1.f / (1.f + expf(-(iz + hz)));
        float n = tanhf(inn + r * hn);
        float hv = (1.f - z) * n + z * hid[h];
        g_hnew[h] = hv;
        out[VN + h] = hv;   // h_new output
    }
}

// output logits: warp per row, 16 rows per 512-thread block, h_new in shared.
// Also emits per-block (max, expsum) partials for split log-sum-exp.
__global__ void __launch_bounds__(512) k_logits(const float* out_W, const float* out_b) {
    __shared__ float4 h4s[HN / 4];
    __shared__ float rowv[LOGITS_ROWS];
    int t = threadIdx.x;
    const float4* h4 = (const float4*)g_hnew;
    h4s[t] = h4[t];          // 512 threads cover all 512 float4
    __syncthreads();
    int lane = t & 31, warp = t >> 5;
    int row = blockIdx.x * LOGITS_ROWS + warp;
    const float4* w4 = (const float4*)(out_W + (long)row * HN);
    float s = 0.f;
#pragma unroll
    for (int k = 0; k < 16; k++) {
        float4 a = w4[lane + 32 * k];
        float4 c = h4s[lane + 32 * k];
        s += a.x * c.x + a.y * c.y + a.z * c.z + a.w * c.w;
    }
    s = warpSum(s);
    if (lane == 0) {
        s += out_b[row];
        g_vlogits[row] = s;
        rowv[warp] = s;
    }
    __syncthreads();
    if (t == 0) {
        float lm = rowv[0];
#pragma unroll
        for (int i = 1; i < LOGITS_ROWS; i++) lm = fmaxf(lm, rowv[i]);
        float ls = 0.f;
#pragma unroll
        for (int i = 0; i < LOGITS_ROWS; i++) ls += expf(rowv[i] - lm);
        g_bmax[blockIdx.x] = lm;
        g_bsum[blockIdx.x] = ls;
        atomicMax(&g_maxbits, fenc(lm));   // deterministic (max order-independent)
    }
}

// combine 3125 split-softmax partials -> logZ (single block, deterministic tree)
__global__ void __launch_bounds__(1024) k_logz() {
    __shared__ float red[1024];
    int t = threadIdx.x;
    float gm = fdec(g_maxbits);
    float s = 0.f;
    for (int i = t; i < NLB; i += 1024) s += g_bsum[i] * expf(g_bmax[i] - gm);
    red[t] = s;
    __syncthreads();
    for (int st = 512; st; st >>= 1) {
        if (t < st) red[t] += red[t + st];
        __syncthreads();
    }
    if (t == 0) g_logZ = gm + logf(red[0]);
}

__global__ void k_writeout(float* out) {
    int i = blockIdx.x * 256 + threadIdx.x;   // float4 index
    if (i < VN / 4) {
        float4 v = ((const float4*)g_vlogits)[i];
        float z = g_logZ;
        v.x -= z; v.y -= z; v.z -= z; v.w -= z;
        ((float4*)out)[i] = v;
    }
}

extern "C" void kernel_launch(void* const* d_in, const int* in_sizes, int n_in,
                              void* d_out, int out_size) {
    const int*   tok    = (const int*)d_in[0];
    const float* hid    = (const float*)d_in[1];
    const float* enc    = (const float*)d_in[2];
    const float* emb    = (const float*)d_in[3];
    const float* attn_W = (const float*)d_in[4];
    const float* attn_b = (const float*)d_in[5];
    const float* comb_W = (const float*)d_in[6];
    const float* comb_b = (const float*)d_in[7];
    const float* W_ih   = (const float*)d_in[8];
    const float* W_hh   = (const float*)d_in[9];
    const float* b_ih   = (const float*)d_in[10];
    const float* b_hh   = (const float*)d_in[11];
    const float* out_W  = (const float*)d_in[12];
    const float* out_b  = (const float*)d_in[13];
    float* out = (float*)d_out;

    k_attnlogits_gh<<<LN + H3, 256>>>(tok, hid, emb, attn_W, attn_b, W_hh, b_hh);
    k_attnapply<<<NCHUNK * 2, 256>>>(enc, out);
    k_attnapply_sum<<<HN / 256, 256>>>();
    k_combine<<<HN, 256>>>(tok, emb, comb_W, comb_b);
    k_gru<<<HN, 256>>>(hid, W_ih, b_ih, out);
    k_logits<<<NLB, 512>>>(out_W, out_b);
    k_logz<<<1, 1024>>>();
    k_writeout<<<(VN / 4 + 255) / 256, 256>>>(out);
}